// round 11
// baseline (speedup 1.0000x reference)
#include <cuda_runtime.h>
#include <cuda_fp16.h>
#include <cstdint>

#define NMAX 100000
#define EMAX 3200000
#define SCAN_BLK 1024
#define LOG2E 1.4426950408889634f

// ---------------- device scratch ----------------
// per node: 128 floats. lane l owns float4 at [n*128 + 4l] = {lin[2l], lin[2l+1], asrc_s[2l], asrc_s[2l+1]}
__device__ __align__(16) float  g_projf[(size_t)NMAX * 128];
__device__ __align__(16) float  g_y[(size_t)NMAX * 64];
__device__ __align__(16) float4 g_pos4[NMAX];
__device__ __align__(16) float4 g_edge[EMAX];   // {src_as_float, rx, ry, rz}
__device__ int g_count[NMAX];
__device__ int g_offset[NMAX + 1];
__device__ int g_cursor[NMAX];
__device__ long long g_scan_state[128];
__device__ int g_scan_count;
__device__ int g_scan_done;

// ---------------- f32x2 packed helpers (sm_100a) ----------------
typedef unsigned long long u64;

__device__ __forceinline__ u64 pack2(float lo, float hi) {
    u64 r;
    asm("mov.b64 %0, {%1, %2};" : "=l"(r) : "f"(lo), "f"(hi));
    return r;
}
__device__ __forceinline__ void unpack2(u64 v, float& lo, float& hi) {
    asm("mov.b64 {%0, %1}, %2;" : "=f"(lo), "=f"(hi) : "l"(v));
}
__device__ __forceinline__ u64 fma2(u64 a, u64 b, u64 c) {
    u64 r;
    asm("fma.rn.f32x2 %0, %1, %2, %3;" : "=l"(r) : "l"(a), "l"(b), "l"(c));
    return r;
}
__device__ __forceinline__ u64 add2(u64 a, u64 b) {
    u64 r;
    asm("add.rn.f32x2 %0, %1, %2;" : "=l"(r) : "l"(a), "l"(b));
    return r;
}
__device__ __forceinline__ float ex2(float x) {
    float y;
    asm("ex2.approx.ftz.f32 %0, %1;" : "=f"(y) : "f"(x));
    return y;
}

// ---------------- per-block edge dtype sniff ----------------
__device__ __forceinline__ int sniff_is64(const void* ei) {
    const int* p = (const int*)ei;
    int is64 = 1;
#pragma unroll
    for (int i = 1; i < 16; i += 2)
        if (__ldg(&p[i]) != 0) is64 = 0;
    return is64;
}

// ---------------- fused prep + node projections ----------------
#define SX_STRIDE 68
__global__ __launch_bounds__(128) void prepproj_kernel(
    const float* __restrict__ x,
    const float* __restrict__ pos,
    const float* __restrict__ W_lin,
    const float* __restrict__ W_src,
    int N)
{
    const int base = blockIdx.x * 64;

    if (threadIdx.x < 64) {
        int n = base + threadIdx.x;
        if (n < N) {
            g_count[n] = 0;
            g_pos4[n] = make_float4(pos[3 * n + 0], pos[3 * n + 1], pos[3 * n + 2], 0.f);
        }
    }
    if (blockIdx.x == 0) {
        if (threadIdx.x < 128) g_scan_state[threadIdx.x] = 0;
        if (threadIdx.x == 0) { g_scan_count = 0; g_scan_done = 0; }
    }

    const int c  = threadIdx.x;
    const int m  = c >> 6;            // 0 = lin, 1 = a_src (pre-scaled by log2e)
    const int cc = c & 63;
    const int h  = cc >> 4;
    const int k  = cc & 15;
    const int fidx = 4 * (cc >> 1) + (cc & 1) + 2 * m;
    const float scale = m ? LOG2E : 1.f;
    const float* W = m ? W_src : W_lin;

    float w[64];
#pragma unroll
    for (int j = 0; j < 64; j++) w[j] = __ldg(&W[h * 1024 + j * 16 + k]) * scale;

    __shared__ float sx[64 * SX_STRIDE];

    for (int f = threadIdx.x; f < 64 * 16; f += 128) {
        int node = f >> 4;
        int j4 = f & 15;
        int gn = base + node;
        if (gn >= N) gn = N - 1;
        float4 v = ((const float4*)x)[(size_t)gn * 16 + j4];
        int j = j4 * 4;
        sx[(j + 0) * SX_STRIDE + node] = v.x;
        sx[(j + 1) * SX_STRIDE + node] = v.y;
        sx[(j + 2) * SX_STRIDE + node] = v.z;
        sx[(j + 3) * SX_STRIDE + node] = v.w;
    }
    __syncthreads();

#pragma unroll
    for (int p = 0; p < 2; p++) {
        float acc[32];
#pragma unroll
        for (int r = 0; r < 32; r++) acc[r] = 0.f;
        for (int j = 0; j < 64; j++) {
            const float4* row = (const float4*)(sx + j * SX_STRIDE + p * 32);
            float wj = w[j];
#pragma unroll
            for (int q = 0; q < 8; q++) {
                float4 v = row[q];
                acc[q * 4 + 0] = fmaf(v.x, wj, acc[q * 4 + 0]);
                acc[q * 4 + 1] = fmaf(v.y, wj, acc[q * 4 + 1]);
                acc[q * 4 + 2] = fmaf(v.z, wj, acc[q * 4 + 2]);
                acc[q * 4 + 3] = fmaf(v.w, wj, acc[q * 4 + 3]);
            }
        }
#pragma unroll
        for (int r = 0; r < 32; r++) {
            int gn = base + p * 32 + r;
            if (gn < N) g_projf[(size_t)gn * 128 + fidx] = acc[r];
        }
    }
}

// ---------------- histogram of dst ----------------
__global__ __launch_bounds__(256) void hist_kernel(const void* __restrict__ ei, int E) {
    __shared__ int s_is64;
    if (threadIdx.x == 0) s_is64 = sniff_is64(ei);
    __syncthreads();
    int t = blockIdx.x * blockDim.x + threadIdx.x;
    if (t >= E) return;
    int d;
    if (s_is64) d = (int)((const long long*)ei)[(size_t)E + t];
    else        d = ((const int*)ei)[(size_t)E + t];
    atomicAdd(&g_count[d], 1);
}

// ---------------- fused scan (decoupled lookback) + scatter edge records ----------------
__global__ __launch_bounds__(SCAN_BLK) void scan_scatter_kernel(
    const void* __restrict__ ei, int N, int E, int nscan)
{
    __shared__ int s_warp[32];
    __shared__ int s_prefix;
    __shared__ int s_is64;

    const int tid = threadIdx.x;
    const int b = blockIdx.x;
    const int lane = tid & 31;
    const int wid = tid >> 5;

    if (b < nscan) {
        const int i = b * SCAN_BLK + tid;
        int v = (i < N) ? g_count[i] : 0;

        int incl = v;
#pragma unroll
        for (int ofs = 1; ofs < 32; ofs <<= 1) {
            int t = __shfl_up_sync(0xffffffffu, incl, ofs);
            if (lane >= ofs) incl += t;
        }
        if (lane == 31) s_warp[wid] = incl;
        __syncthreads();

        if (wid == 0) {
            int wv = s_warp[lane];
#pragma unroll
            for (int ofs = 1; ofs < 32; ofs <<= 1) {
                int t = __shfl_up_sync(0xffffffffu, wv, ofs);
                if (lane >= ofs) wv += t;
            }
            s_warp[lane] = wv;
        }
        __syncthreads();

        int warp_excl = (wid == 0) ? 0 : s_warp[wid - 1];
        int block_incl = incl + warp_excl;
        int block_total = s_warp[31];

        if (tid == 0) {
            volatile long long* st = (volatile long long*)g_scan_state;
            int prefix = 0;
            if (b == 0) {
                __threadfence();
                st[0] = ((long long)2 << 32) | (unsigned)block_total;
            } else {
                __threadfence();
                st[b] = ((long long)1 << 32) | (unsigned)block_total;
                int j = b - 1;
                while (j >= 0) {
                    long long s = st[j];
                    int flag = (int)(s >> 32);
                    if (flag == 2) { prefix += (int)(unsigned)s; break; }
                    if (flag == 1) { prefix += (int)(unsigned)s; j--; }
                }
                __threadfence();
                st[b] = ((long long)2 << 32) | (unsigned)(prefix + block_total);
            }
            s_prefix = prefix;
        }
        __syncthreads();

        int off = s_prefix + block_incl - v;
        if (i < N) {
            g_offset[i] = off;
            g_cursor[i] = off;
            if (i == N - 1) g_offset[N] = E;
        }
        __syncthreads();
        if (tid == 0) {
            __threadfence();
            int done = atomicAdd(&g_scan_count, 1);
            if (done == nscan - 1) atomicExch(&g_scan_done, 1);
        }
    }

    if (tid == 0) {
        while (atomicAdd(&g_scan_done, 0) == 0) { __nanosleep(64); }
        s_is64 = sniff_is64(ei);
    }
    __syncthreads();

    int t = b * SCAN_BLK + tid;
    if (t < E) {
        int s, d;
        if (s_is64) {
            s = (int)((const long long*)ei)[t];
            d = (int)((const long long*)ei)[(size_t)E + t];
        } else {
            s = ((const int*)ei)[t];
            d = ((const int*)ei)[(size_t)E + t];
        }
        int idx = atomicAdd(&g_cursor[d], 1);
        float4 ps = __ldg(&g_pos4[s]);
        float4 pd = __ldg(&g_pos4[d]);
        float4 er;
        er.x = __int_as_float(s);
        er.y = ps.x - pd.x;
        er.z = ps.y - pd.y;
        er.w = ps.z - pd.z;
        g_edge[idx] = er;
    }
}

// ---------------- per-destination-node attention: warp per node, f32x2 packed ----------------
__global__ __launch_bounds__(256, 6) void node_kernel(
    const float* __restrict__ W_pos,
    const float* __restrict__ b_pos,
    int N)
{
    const int warp = threadIdx.x >> 5;
    const int l = threadIdx.x & 31;
    const int n = blockIdx.x * 8 + warp;
    if (n >= N) return;

    const int c0 = 2 * l;
    const int h  = c0 >> 4;
    const int k0 = c0 & 15;
    const int k1 = k0 + 1;

    // packed per-channel-pair constants
    const u64 W0 = pack2(__ldg(&W_pos[h * 48 + 0  + k0]), __ldg(&W_pos[h * 48 + 0  + k1]));
    const u64 W1 = pack2(__ldg(&W_pos[h * 48 + 16 + k0]), __ldg(&W_pos[h * 48 + 16 + k1]));
    const u64 W2 = pack2(__ldg(&W_pos[h * 48 + 32 + k0]), __ldg(&W_pos[h * 48 + 32 + k1]));
    const u64 Bp = pack2(__ldg(&b_pos[h * 16 + k0]), __ldg(&b_pos[h * 16 + k1]));
    const u64 L2E2 = pack2(LOG2E, LOG2E);

    const int off = g_offset[n];
    const int end = g_offset[n + 1];

    u64 DEN = pack2(0.f, 0.f);
    u64 AC  = pack2(0.f, 0.f);

    // per node: 512 B = 32 x 16B elements; lane l owns element l of the node's 32.
    const ulonglong2* prow = (const ulonglong2*)g_projf;

#pragma unroll 4
    for (int e = off; e < end; e++) {
        float4 er = __ldg(&g_edge[e]);                       // broadcast, 1 wavefront
        int s = __float_as_int(er.x);
        ulonglong2 v = __ldg(&prow[(size_t)s * 32 + l]);     // v.x = lin pair, v.y = vaS pair

        u64 RX = pack2(er.y, er.y);
        u64 RY = pack2(er.z, er.z);
        u64 RZ = pack2(er.w, er.w);

        u64 D = fma2(RX, W0, fma2(RY, W1, fma2(RZ, W2, Bp)));   // delta pair
        u64 T = fma2(D, L2E2, v.y);                              // log2e*delta + vaS

        float t0, t1;
        unpack2(T, t0, t1);
        float e0 = ex2(t0);
        float e1 = ex2(t1);
        u64 E2 = pack2(e0, e1);

        DEN = add2(DEN, E2);
        u64 VLD = add2(v.x, D);                                  // lin + delta
        AC = fma2(E2, VLD, AC);
    }

    float den0, den1, ac0, ac1;
    unpack2(DEN, den0, den1);
    unpack2(AC, ac0, ac1);

    float2 r;
    r.x = ac0 / (den0 + 1e-16f);
    r.y = ac1 / (den1 + 1e-16f);
    ((float2*)g_y)[(size_t)n * 32 + l] = r;
}

// ---------------- register-tiled MLP ----------------
__global__ __launch_bounds__(256) void mlp_kernel(
    const float* __restrict__ W1, const float* __restrict__ b1,
    const float* __restrict__ W2, const float* __restrict__ b2,
    float* __restrict__ out, int N)
{
    __shared__ float sy[64 * 64];
    __shared__ float sh_[64 * 64];
    __shared__ float sW[64 * 64];

    const int tid = threadIdx.x;
    const int og = tid >> 5;
    const int ng = tid & 31;
    const int base = blockIdx.x * 64;

    for (int f = tid; f < 64 * 16; f += 256) {
        int node = f >> 4;
        int j4 = f & 15;
        int gn = base + node;
        float4 v = (gn < N) ? ((const float4*)g_y)[(size_t)gn * 16 + j4]
                            : make_float4(0.f, 0.f, 0.f, 0.f);
        int cch = j4 * 4;
        sy[(cch + 0) * 64 + node] = v.x;
        sy[(cch + 1) * 64 + node] = v.y;
        sy[(cch + 2) * 64 + node] = v.z;
        sy[(cch + 3) * 64 + node] = v.w;
    }
    for (int f = tid; f < 1024; f += 256)
        ((float4*)sW)[f] = ((const float4*)W1)[f];
    __syncthreads();

    float acc[16];
    {
        float4 ba = *(const float4*)(b1 + og * 8);
        float4 bb = *(const float4*)(b1 + og * 8 + 4);
        acc[0]=ba.x; acc[1]=ba.y; acc[2]=ba.z; acc[3]=ba.w;
        acc[4]=bb.x; acc[5]=bb.y; acc[6]=bb.z; acc[7]=bb.w;
#pragma unroll
        for (int r = 0; r < 8; r++) acc[8 + r] = acc[r];
    }
#pragma unroll 8
    for (int k = 0; k < 64; k++) {
        float2 yv = *(const float2*)(sy + k * 64 + 2 * ng);
        float4 wa = *(const float4*)(sW + k * 64 + og * 8);
        float4 wb = *(const float4*)(sW + k * 64 + og * 8 + 4);
        acc[0]  = fmaf(yv.x, wa.x, acc[0]);
        acc[1]  = fmaf(yv.x, wa.y, acc[1]);
        acc[2]  = fmaf(yv.x, wa.z, acc[2]);
        acc[3]  = fmaf(yv.x, wa.w, acc[3]);
        acc[4]  = fmaf(yv.x, wb.x, acc[4]);
        acc[5]  = fmaf(yv.x, wb.y, acc[5]);
        acc[6]  = fmaf(yv.x, wb.z, acc[6]);
        acc[7]  = fmaf(yv.x, wb.w, acc[7]);
        acc[8]  = fmaf(yv.y, wa.x, acc[8]);
        acc[9]  = fmaf(yv.y, wa.y, acc[9]);
        acc[10] = fmaf(yv.y, wa.z, acc[10]);
        acc[11] = fmaf(yv.y, wa.w, acc[11]);
        acc[12] = fmaf(yv.y, wb.x, acc[12]);
        acc[13] = fmaf(yv.y, wb.y, acc[13]);
        acc[14] = fmaf(yv.y, wb.z, acc[14]);
        acc[15] = fmaf(yv.y, wb.w, acc[15]);
    }
#pragma unroll
    for (int oo = 0; oo < 8; oo++) {
        float2 hv;
        hv.x = fmaxf(acc[oo], 0.f);
        hv.y = fmaxf(acc[8 + oo], 0.f);
        *(float2*)(sh_ + (og * 8 + oo) * 64 + 2 * ng) = hv;
    }
    __syncthreads();

    for (int f = tid; f < 1024; f += 256)
        ((float4*)sW)[f] = ((const float4*)W2)[f];
    __syncthreads();

    {
        float4 ba = *(const float4*)(b2 + og * 8);
        float4 bb = *(const float4*)(b2 + og * 8 + 4);
        acc[0]=ba.x; acc[1]=ba.y; acc[2]=ba.z; acc[3]=ba.w;
        acc[4]=bb.x; acc[5]=bb.y; acc[6]=bb.z; acc[7]=bb.w;
#pragma unroll
        for (int r = 0; r < 8; r++) acc[8 + r] = acc[r];
    }
#pragma unroll 8
    for (int k = 0; k < 64; k++) {
        float2 hv = *(const float2*)(sh_ + k * 64 + 2 * ng);
        float4 wa = *(const float4*)(sW + k * 64 + og * 8);
        float4 wb = *(const float4*)(sW + k * 64 + og * 8 + 4);
        acc[0]  = fmaf(hv.x, wa.x, acc[0]);
        acc[1]  = fmaf(hv.x, wa.y, acc[1]);
        acc[2]  = fmaf(hv.x, wa.z, acc[2]);
        acc[3]  = fmaf(hv.x, wa.w, acc[3]);
        acc[4]  = fmaf(hv.x, wb.x, acc[4]);
        acc[5]  = fmaf(hv.x, wb.y, acc[5]);
        acc[6]  = fmaf(hv.x, wb.z, acc[6]);
        acc[7]  = fmaf(hv.x, wb.w, acc[7]);
        acc[8]  = fmaf(hv.y, wa.x, acc[8]);
        acc[9]  = fmaf(hv.y, wa.y, acc[9]);
        acc[10] = fmaf(hv.y, wa.z, acc[10]);
        acc[11] = fmaf(hv.y, wa.w, acc[11]);
        acc[12] = fmaf(hv.y, wb.x, acc[12]);
        acc[13] = fmaf(hv.y, wb.y, acc[13]);
        acc[14] = fmaf(hv.y, wb.z, acc[14]);
        acc[15] = fmaf(hv.y, wb.w, acc[15]);
    }

#pragma unroll
    for (int nn = 0; nn < 2; nn++) {
        int gn = base + 2 * ng + nn;
        if (gn < N) {
            float4 oa, ob;
            oa.x = acc[8 * nn + 0]; oa.y = acc[8 * nn + 1];
            oa.z = acc[8 * nn + 2]; oa.w = acc[8 * nn + 3];
            ob.x = acc[8 * nn + 4]; ob.y = acc[8 * nn + 5];
            ob.z = acc[8 * nn + 6]; ob.w = acc[8 * nn + 7];
            *(float4*)(out + (size_t)gn * 64 + og * 8)     = oa;
            *(float4*)(out + (size_t)gn * 64 + og * 8 + 4) = ob;
        }
    }
}

// ---------------- host ----------------
extern "C" void kernel_launch(void* const* d_in, const int* in_sizes, int n_in,
                              void* d_out, int out_size) {
    const float* x     = (const float*)d_in[0];
    const float* pos   = (const float*)d_in[1];
    const void*  ei    = d_in[2];
    const float* W_lin = (const float*)d_in[3];
    const float* W_src = (const float*)d_in[4];
    // d_in[5] = W_dst (cancels in the per-dst softmax)
    const float* W_pos = (const float*)d_in[6];
    const float* b_pos = (const float*)d_in[7];
    const float* W1    = (const float*)d_in[8];
    const float* b1    = (const float*)d_in[9];
    const float* W2    = (const float*)d_in[10];
    const float* b2    = (const float*)d_in[11];
    float* out = (float*)d_out;

    const int N = in_sizes[0] / 64;
    const int E = in_sizes[2] / 2;
    const int nscan = (N + SCAN_BLK - 1) / SCAN_BLK;
    int nss = (E + SCAN_BLK - 1) / SCAN_BLK;
    if (nss < nscan) nss = nscan;

    prepproj_kernel<<<(N + 63) / 64, 128>>>(x, pos, W_lin, W_src, N);
    hist_kernel<<<(E + 255) / 256, 256>>>(ei, E);
    scan_scatter_kernel<<<nss, SCAN_BLK>>>(ei, N, E, nscan);
    node_kernel<<<(N + 7) / 8, 256>>>(W_pos, b_pos, N);
    mlp_kernel<<<(N + 63) / 64, 256>>>(W1, b1, W2, b2, out, N);
}

// round 12
// speedup vs baseline: 1.0019x; 1.0019x over previous
#include <cuda_runtime.h>
#include <cstdint>

#define NMAX 100000
#define EMAX 3200000
#define SCAN_BLK 1024
#define LOG2E 1.4426950408889634f

// ---------------- device scratch ----------------
// per node: 128 floats; lane l owns float4 at [n*128+4l] = {lin[2l], lin[2l+1], asrc*log2e[2l], [2l+1]}
__device__ __align__(16) float  g_projf[(size_t)NMAX * 128];
__device__ __align__(16) float4 g_pos4[NMAX];
__device__ __align__(16) float4 g_edge[EMAX];   // {src_as_float, rx, ry, rz}
__device__ int g_count[NMAX];
__device__ int g_offset[NMAX + 1];
__device__ int g_cursor[NMAX];
__device__ long long g_scan_state[128];
__device__ int g_scan_count;
__device__ int g_scan_done;

__device__ __forceinline__ float ex2(float x) {
    float y;
    asm("ex2.approx.ftz.f32 %0, %1;" : "=f"(y) : "f"(x));
    return y;
}

__device__ __forceinline__ int sniff_is64(const void* ei) {
    const int* p = (const int*)ei;
    int is64 = 1;
#pragma unroll
    for (int i = 1; i < 16; i += 2)
        if (__ldg(&p[i]) != 0) is64 = 0;
    return is64;
}

// ---------------- zero: counters + scan state ----------------
__global__ void zero_kernel(int N) {
    int i = blockIdx.x * blockDim.x + threadIdx.x;
    if (i < N) g_count[i] = 0;
    if (i < 128) g_scan_state[i] = 0;
    if (i == 0) { g_scan_count = 0; g_scan_done = 0; }
}

// ---------------- fused proj (blocks < PB) + hist (blocks >= PB) ----------------
#define SX_STRIDE 68
__global__ __launch_bounds__(128) void projhist_kernel(
    const float* __restrict__ x,
    const float* __restrict__ pos,
    const float* __restrict__ W_lin,
    const float* __restrict__ W_src,
    const void* __restrict__ ei,
    int N, int E, int PB)
{
    if (blockIdx.x >= PB) {
        // ---- histogram role: 2048 edges per block ----
        __shared__ int s_is64;
        if (threadIdx.x == 0) s_is64 = sniff_is64(ei);
        __syncthreads();
        int base = (blockIdx.x - PB) * 2048;
        if (s_is64) {
            const long long* p = (const long long*)ei + E;
#pragma unroll 4
            for (int i = 0; i < 16; i++) {
                int t = base + i * 128 + threadIdx.x;
                if (t < E) atomicAdd(&g_count[(int)p[t]], 1);
            }
        } else {
            const int* p = (const int*)ei + E;
#pragma unroll 4
            for (int i = 0; i < 16; i++) {
                int t = base + i * 128 + threadIdx.x;
                if (t < E) atomicAdd(&g_count[p[t]], 1);
            }
        }
        return;
    }

    // ---- proj role: 64 nodes per block ----
    const int base = blockIdx.x * 64;

    if (threadIdx.x < 64) {
        int n = base + threadIdx.x;
        if (n < N)
            g_pos4[n] = make_float4(pos[3 * n + 0], pos[3 * n + 1], pos[3 * n + 2], 0.f);
    }

    const int c  = threadIdx.x;
    const int m  = c >> 6;            // 0 = lin, 1 = a_src (pre-scaled by log2e)
    const int cc = c & 63;
    const int h  = cc >> 4;
    const int k  = cc & 15;
    const int fidx = 4 * (cc >> 1) + (cc & 1) + 2 * m;
    const float scale = m ? LOG2E : 1.f;
    const float* W = m ? W_src : W_lin;

    float w[64];
#pragma unroll
    for (int j = 0; j < 64; j++) w[j] = __ldg(&W[h * 1024 + j * 16 + k]) * scale;

    __shared__ float sx[64 * SX_STRIDE];

    for (int f = threadIdx.x; f < 64 * 16; f += 128) {
        int node = f >> 4;
        int j4 = f & 15;
        int gn = base + node;
        if (gn >= N) gn = N - 1;
        float4 v = ((const float4*)x)[(size_t)gn * 16 + j4];
        int j = j4 * 4;
        sx[(j + 0) * SX_STRIDE + node] = v.x;
        sx[(j + 1) * SX_STRIDE + node] = v.y;
        sx[(j + 2) * SX_STRIDE + node] = v.z;
        sx[(j + 3) * SX_STRIDE + node] = v.w;
    }
    __syncthreads();

#pragma unroll
    for (int p = 0; p < 2; p++) {
        float acc[32];
#pragma unroll
        for (int r = 0; r < 32; r++) acc[r] = 0.f;
        for (int j = 0; j < 64; j++) {
            const float4* row = (const float4*)(sx + j * SX_STRIDE + p * 32);
            float wj = w[j];
#pragma unroll
            for (int q = 0; q < 8; q++) {
                float4 v = row[q];
                acc[q * 4 + 0] = fmaf(v.x, wj, acc[q * 4 + 0]);
                acc[q * 4 + 1] = fmaf(v.y, wj, acc[q * 4 + 1]);
                acc[q * 4 + 2] = fmaf(v.z, wj, acc[q * 4 + 2]);
                acc[q * 4 + 3] = fmaf(v.w, wj, acc[q * 4 + 3]);
            }
        }
#pragma unroll
        for (int r = 0; r < 32; r++) {
            int gn = base + p * 32 + r;
            if (gn < N) g_projf[(size_t)gn * 128 + fidx] = acc[r];
        }
    }
}

// ---------------- fused scan (decoupled lookback) + scatter edge records ----------------
__global__ __launch_bounds__(SCAN_BLK) void scan_scatter_kernel(
    const void* __restrict__ ei, int N, int E, int nscan)
{
    __shared__ int s_warp[32];
    __shared__ int s_prefix;
    __shared__ int s_is64;

    const int tid = threadIdx.x;
    const int b = blockIdx.x;
    const int lane = tid & 31;
    const int wid = tid >> 5;

    if (b < nscan) {
        const int i = b * SCAN_BLK + tid;
        int v = (i < N) ? g_count[i] : 0;

        int incl = v;
#pragma unroll
        for (int ofs = 1; ofs < 32; ofs <<= 1) {
            int t = __shfl_up_sync(0xffffffffu, incl, ofs);
            if (lane >= ofs) incl += t;
        }
        if (lane == 31) s_warp[wid] = incl;
        __syncthreads();

        if (wid == 0) {
            int wv = s_warp[lane];
#pragma unroll
            for (int ofs = 1; ofs < 32; ofs <<= 1) {
                int t = __shfl_up_sync(0xffffffffu, wv, ofs);
                if (lane >= ofs) wv += t;
            }
            s_warp[lane] = wv;
        }
        __syncthreads();

        int warp_excl = (wid == 0) ? 0 : s_warp[wid - 1];
        int block_incl = incl + warp_excl;
        int block_total = s_warp[31];

        if (tid == 0) {
            volatile long long* st = (volatile long long*)g_scan_state;
            int prefix = 0;
            if (b == 0) {
                __threadfence();
                st[0] = ((long long)2 << 32) | (unsigned)block_total;
            } else {
                __threadfence();
                st[b] = ((long long)1 << 32) | (unsigned)block_total;
                int j = b - 1;
                while (j >= 0) {
                    long long s = st[j];
                    int flag = (int)(s >> 32);
                    if (flag == 2) { prefix += (int)(unsigned)s; break; }
                    if (flag == 1) { prefix += (int)(unsigned)s; j--; }
                }
                __threadfence();
                st[b] = ((long long)2 << 32) | (unsigned)(prefix + block_total);
            }
            s_prefix = prefix;
        }
        __syncthreads();

        int off = s_prefix + block_incl - v;
        if (i < N) {
            g_offset[i] = off;
            g_cursor[i] = off;
            if (i == N - 1) g_offset[N] = E;
        }
        __syncthreads();
        if (tid == 0) {
            __threadfence();
            int done = atomicAdd(&g_scan_count, 1);
            if (done == nscan - 1) atomicExch(&g_scan_done, 1);
        }
    }

    if (tid == 0) {
        while (atomicAdd(&g_scan_done, 0) == 0) { __nanosleep(64); }
        s_is64 = sniff_is64(ei);
    }
    __syncthreads();

    int t = b * SCAN_BLK + tid;
    if (t < E) {
        int s, d;
        if (s_is64) {
            s = (int)((const long long*)ei)[t];
            d = (int)((const long long*)ei)[(size_t)E + t];
        } else {
            s = ((const int*)ei)[t];
            d = ((const int*)ei)[(size_t)E + t];
        }
        int idx = atomicAdd(&g_cursor[d], 1);
        float4 ps = __ldg(&g_pos4[s]);
        float4 pd = __ldg(&g_pos4[d]);
        float4 er;
        er.x = __int_as_float(s);
        er.y = ps.x - pd.x;
        er.z = ps.y - pd.y;
        er.w = ps.z - pd.z;
        g_edge[idx] = er;
    }
}

// ---------------- fused node attention + MLP: 64 nodes per 512-thread block ----------------
// Phase A: warp w computes 4 nodes (attention), writes y into shared sy[k][node] (stride 65).
// Phase B: y -> relu(y@W1+b1) -> @W2+b2 -> out, all in-block. sy reused as relu buffer.
__global__ __launch_bounds__(512, 3) void nodemlp_kernel(
    const float* __restrict__ W_pos,
    const float* __restrict__ b_pos,
    const float* __restrict__ W1, const float* __restrict__ b1,
    const float* __restrict__ W2, const float* __restrict__ b2,
    float* __restrict__ out, int N)
{
    __shared__ float sy[64 * 65];   // [k][node], padded
    __shared__ float sW[64 * 64];

    const int tid = threadIdx.x;
    const int w = tid >> 5;
    const int l = tid & 31;
    const int base = blockIdx.x * 64;

    // preload W1 while attention runs
    for (int f = tid; f < 1024; f += 512)
        ((float4*)sW)[f] = ((const float4*)W1)[f];

    // ---- Phase A: attention, 4 nodes per warp ----
    const int c0 = 2 * l;
    const int h  = c0 >> 4;
    const int k0 = c0 & 15;
    const int k1 = k0 + 1;

    const float w00 = __ldg(&W_pos[h * 48 + 0  + k0]);
    const float w10 = __ldg(&W_pos[h * 48 + 16 + k0]);
    const float w20 = __ldg(&W_pos[h * 48 + 32 + k0]);
    const float b0  = __ldg(&b_pos[h * 16 + k0]);
    const float w01 = __ldg(&W_pos[h * 48 + 0  + k1]);
    const float w11 = __ldg(&W_pos[h * 48 + 16 + k1]);
    const float w21 = __ldg(&W_pos[h * 48 + 32 + k1]);
    const float b1c = __ldg(&b_pos[h * 16 + k1]);

    const float4* prow = (const float4*)g_projf;

#pragma unroll
    for (int i = 0; i < 4; i++) {
        const int nd = w * 4 + i;
        const int n = base + nd;
        float rx = 0.f, ry = 0.f;
        if (n < N) {
            const int off = g_offset[n];
            const int end = g_offset[n + 1];
            float den0 = 0.f, den1 = 0.f, ac0 = 0.f, ac1 = 0.f;
#pragma unroll 4
            for (int e = off; e < end; e++) {
                float4 er = __ldg(&g_edge[e]);
                int s = __float_as_int(er.x);
                float4 v = __ldg(&prow[(size_t)s * 32 + l]);   // {lin0, lin1, vaS0, vaS1}

                float d0 = fmaf(er.y, w00, fmaf(er.z, w10, fmaf(er.w, w20, b0)));
                float d1 = fmaf(er.y, w01, fmaf(er.z, w11, fmaf(er.w, w21, b1c)));

                float e0 = ex2(fmaf(d0, LOG2E, v.z));
                float e1 = ex2(fmaf(d1, LOG2E, v.w));

                den0 += e0;
                den1 += e1;
                ac0 = fmaf(e0, v.x + d0, ac0);
                ac1 = fmaf(e1, v.y + d1, ac1);
            }
            rx = ac0 / (den0 + 1e-16f);
            ry = ac1 / (den1 + 1e-16f);
        }
        sy[(c0 + 0) * 65 + nd] = rx;
        sy[(c0 + 1) * 65 + nd] = ry;
    }
    __syncthreads();   // sy complete, sW(W1) complete

    // ---- Phase B layer 1: thread = (og: 8 outputs) x (nd: 1 node) ----
    const int og = tid >> 6;       // 0..7
    const int nd = tid & 63;

    float acc[8];
    {
        float4 ba = *(const float4*)(b1 + og * 8);
        float4 bb = *(const float4*)(b1 + og * 8 + 4);
        acc[0]=ba.x; acc[1]=ba.y; acc[2]=ba.z; acc[3]=ba.w;
        acc[4]=bb.x; acc[5]=bb.y; acc[6]=bb.z; acc[7]=bb.w;
    }
#pragma unroll 8
    for (int k = 0; k < 64; k++) {
        float yv = sy[k * 65 + nd];
        float4 wa = *(const float4*)(sW + k * 64 + og * 8);
        float4 wb = *(const float4*)(sW + k * 64 + og * 8 + 4);
        acc[0] = fmaf(yv, wa.x, acc[0]);
        acc[1] = fmaf(yv, wa.y, acc[1]);
        acc[2] = fmaf(yv, wa.z, acc[2]);
        acc[3] = fmaf(yv, wa.w, acc[3]);
        acc[4] = fmaf(yv, wb.x, acc[4]);
        acc[5] = fmaf(yv, wb.y, acc[5]);
        acc[6] = fmaf(yv, wb.z, acc[6]);
        acc[7] = fmaf(yv, wb.w, acc[7]);
    }
    __syncthreads();   // everyone done reading sy (and sW)

    // write relu into sy (reused), load W2
#pragma unroll
    for (int oo = 0; oo < 8; oo++)
        sy[(og * 8 + oo) * 65 + nd] = fmaxf(acc[oo], 0.f);
    for (int f = tid; f < 1024; f += 512)
        ((float4*)sW)[f] = ((const float4*)W2)[f];
    __syncthreads();

    // ---- Phase B layer 2 ----
    {
        float4 ba = *(const float4*)(b2 + og * 8);
        float4 bb = *(const float4*)(b2 + og * 8 + 4);
        acc[0]=ba.x; acc[1]=ba.y; acc[2]=ba.z; acc[3]=ba.w;
        acc[4]=bb.x; acc[5]=bb.y; acc[6]=bb.z; acc[7]=bb.w;
    }
#pragma unroll 8
    for (int k = 0; k < 64; k++) {
        float hv = sy[k * 65 + nd];
        float4 wa = *(const float4*)(sW + k * 64 + og * 8);
        float4 wb = *(const float4*)(sW + k * 64 + og * 8 + 4);
        acc[0] = fmaf(hv, wa.x, acc[0]);
        acc[1] = fmaf(hv, wa.y, acc[1]);
        acc[2] = fmaf(hv, wa.z, acc[2]);
        acc[3] = fmaf(hv, wa.w, acc[3]);
        acc[4] = fmaf(hv, wb.x, acc[4]);
        acc[5] = fmaf(hv, wb.y, acc[5]);
        acc[6] = fmaf(hv, wb.z, acc[6]);
        acc[7] = fmaf(hv, wb.w, acc[7]);
    }

    int gn = base + nd;
    if (gn < N) {
        float4 oa, ob;
        oa.x = acc[0]; oa.y = acc[1]; oa.z = acc[2]; oa.w = acc[3];
        ob.x = acc[4]; ob.y = acc[5]; ob.z = acc[6]; ob.w = acc[7];
        *(float4*)(out + (size_t)gn * 64 + og * 8)     = oa;
        *(float4*)(out + (size_t)gn * 64 + og * 8 + 4) = ob;
    }
}

// ---------------- host ----------------
extern "C" void kernel_launch(void* const* d_in, const int* in_sizes, int n_in,
                              void* d_out, int out_size) {
    const float* x     = (const float*)d_in[0];
    const float* pos   = (const float*)d_in[1];
    const void*  ei    = d_in[2];
    const float* W_lin = (const float*)d_in[3];
    const float* W_src = (const float*)d_in[4];
    // d_in[5] = W_dst (cancels in the per-dst softmax)
    const float* W_pos = (const float*)d_in[6];
    const float* b_pos = (const float*)d_in[7];
    const float* W1    = (const float*)d_in[8];
    const float* b1    = (const float*)d_in[9];
    const float* W2    = (const float*)d_in[10];
    const float* b2    = (const float*)d_in[11];
    float* out = (float*)d_out;

    const int N = in_sizes[0] / 64;
    const int E = in_sizes[2] / 2;
    const int nscan = (N + SCAN_BLK - 1) / SCAN_BLK;
    int nss = (E + SCAN_BLK - 1) / SCAN_BLK;
    if (nss < nscan) nss = nscan;

    const int PB = (N + 63) / 64;                  // proj blocks
    const int HB = (E + 2047) / 2048;              // hist blocks

    zero_kernel<<<(N + 1023) / 1024, 1024>>>(N);
    projhist_kernel<<<PB + HB, 128>>>(x, pos, W_lin, W_src, ei, N, E, PB);
    scan_scatter_kernel<<<nss, SCAN_BLK>>>(ei, N, E, nscan);
    nodemlp_kernel<<<(N + 63) / 64, 512>>>(W_pos, b_pos, W1, b1, W2, b2, out, N);
}

// round 14
// speedup vs baseline: 1.0377x; 1.0357x over previous
#include <cuda_runtime.h>
#include <cstdint>

#define NMAX 100000
#define EMAX 3200000
#define SCAN_BLK 1024
#define LOG2E 1.4426950408889634f

// ---------------- device scratch ----------------
// per node: 128 floats; lane l owns float4 at [n*128+4l] = {lin[2l], lin[2l+1], asrc*log2e[2l], [2l+1]}
__device__ __align__(16) float  g_projf[(size_t)NMAX * 128];
__device__ __align__(16) float  g_y[(size_t)NMAX * 64];
__device__ __align__(16) float4 g_pos4[NMAX];
__device__ __align__(16) float4 g_edge[EMAX];   // {src_as_float, rx, ry, rz}
__device__ int g_count[NMAX];
__device__ int g_offset[NMAX + 1];
__device__ int g_cursor[NMAX];
__device__ long long g_scan_state[128];
__device__ int g_scan_count;
__device__ int g_scan_done;

__device__ __forceinline__ float ex2(float x) {
    float y;
    asm("ex2.approx.ftz.f32 %0, %1;" : "=f"(y) : "f"(x));
    return y;
}

__device__ __forceinline__ int sniff_is64(const void* ei) {
    const int* p = (const int*)ei;
    int is64 = 1;
#pragma unroll
    for (int i = 1; i < 16; i += 2)
        if (__ldg(&p[i]) != 0) is64 = 0;
    return is64;
}

// ---------------- zero: counters + scan state ----------------
__global__ void zero_kernel(int N) {
    int i = blockIdx.x * blockDim.x + threadIdx.x;
    if (i < N) g_count[i] = 0;
    if (i < 128) g_scan_state[i] = 0;
    if (i == 0) { g_scan_count = 0; g_scan_done = 0; }
}

// ---------------- fused proj (blocks < PB) + hist (blocks >= PB) ----------------
#define SX_STRIDE 68
__global__ __launch_bounds__(128) void projhist_kernel(
    const float* __restrict__ x,
    const float* __restrict__ pos,
    const float* __restrict__ W_lin,
    const float* __restrict__ W_src,
    const void* __restrict__ ei,
    int N, int E, int PB)
{
    if (blockIdx.x >= PB) {
        // ---- histogram role: 2048 edges per block ----
        __shared__ int s_is64;
        if (threadIdx.x == 0) s_is64 = sniff_is64(ei);
        __syncthreads();
        int base = (blockIdx.x - PB) * 2048;
        if (s_is64) {
            const long long* p = (const long long*)ei + E;
#pragma unroll 4
            for (int i = 0; i < 16; i++) {
                int t = base + i * 128 + threadIdx.x;
                if (t < E) atomicAdd(&g_count[(int)p[t]], 1);
            }
        } else {
            const int* p = (const int*)ei + E;
#pragma unroll 4
            for (int i = 0; i < 16; i++) {
                int t = base + i * 128 + threadIdx.x;
                if (t < E) atomicAdd(&g_count[p[t]], 1);
            }
        }
        return;
    }

    // ---- proj role: 64 nodes per block ----
    const int base = blockIdx.x * 64;

    if (threadIdx.x < 64) {
        int n = base + threadIdx.x;
        if (n < N)
            g_pos4[n] = make_float4(pos[3 * n + 0], pos[3 * n + 1], pos[3 * n + 2], 0.f);
    }

    const int c  = threadIdx.x;
    const int m  = c >> 6;            // 0 = lin, 1 = a_src (pre-scaled by log2e)
    const int cc = c & 63;
    const int h  = cc >> 4;
    const int k  = cc & 15;
    const int fidx = 4 * (cc >> 1) + (cc & 1) + 2 * m;
    const float scale = m ? LOG2E : 1.f;
    const float* W = m ? W_src : W_lin;

    float w[64];
#pragma unroll
    for (int j = 0; j < 64; j++) w[j] = __ldg(&W[h * 1024 + j * 16 + k]) * scale;

    __shared__ float sx[64 * SX_STRIDE];

    for (int f = threadIdx.x; f < 64 * 16; f += 128) {
        int node = f >> 4;
        int j4 = f & 15;
        int gn = base + node;
        if (gn >= N) gn = N - 1;
        float4 v = ((const float4*)x)[(size_t)gn * 16 + j4];
        int j = j4 * 4;
        sx[(j + 0) * SX_STRIDE + node] = v.x;
        sx[(j + 1) * SX_STRIDE + node] = v.y;
        sx[(j + 2) * SX_STRIDE + node] = v.z;
        sx[(j + 3) * SX_STRIDE + node] = v.w;
    }
    __syncthreads();

#pragma unroll
    for (int p = 0; p < 2; p++) {
        float acc[32];
#pragma unroll
        for (int r = 0; r < 32; r++) acc[r] = 0.f;
        for (int j = 0; j < 64; j++) {
            const float4* row = (const float4*)(sx + j * SX_STRIDE + p * 32);
            float wj = w[j];
#pragma unroll
            for (int q = 0; q < 8; q++) {
                float4 v = row[q];
                acc[q * 4 + 0] = fmaf(v.x, wj, acc[q * 4 + 0]);
                acc[q * 4 + 1] = fmaf(v.y, wj, acc[q * 4 + 1]);
                acc[q * 4 + 2] = fmaf(v.z, wj, acc[q * 4 + 2]);
                acc[q * 4 + 3] = fmaf(v.w, wj, acc[q * 4 + 3]);
            }
        }
#pragma unroll
        for (int r = 0; r < 32; r++) {
            int gn = base + p * 32 + r;
            if (gn < N) g_projf[(size_t)gn * 128 + fidx] = acc[r];
        }
    }
}

// ---------------- fused scan (decoupled lookback) + scatter edge records ----------------
__global__ __launch_bounds__(SCAN_BLK) void scan_scatter_kernel(
    const void* __restrict__ ei, int N, int E, int nscan)
{
    __shared__ int s_warp[32];
    __shared__ int s_prefix;
    __shared__ int s_is64;

    const int tid = threadIdx.x;
    const int b = blockIdx.x;
    const int lane = tid & 31;
    const int wid = tid >> 5;

    if (b < nscan) {
        const int i = b * SCAN_BLK + tid;
        int v = (i < N) ? g_count[i] : 0;

        int incl = v;
#pragma unroll
        for (int ofs = 1; ofs < 32; ofs <<= 1) {
            int t = __shfl_up_sync(0xffffffffu, incl, ofs);
            if (lane >= ofs) incl += t;
        }
        if (lane == 31) s_warp[wid] = incl;
        __syncthreads();

        if (wid == 0) {
            int wv = s_warp[lane];
#pragma unroll
            for (int ofs = 1; ofs < 32; ofs <<= 1) {
                int t = __shfl_up_sync(0xffffffffu, wv, ofs);
                if (lane >= ofs) wv += t;
            }
            s_warp[lane] = wv;
        }
        __syncthreads();

        int warp_excl = (wid == 0) ? 0 : s_warp[wid - 1];
        int block_incl = incl + warp_excl;
        int block_total = s_warp[31];

        if (tid == 0) {
            volatile long long* st = (volatile long long*)g_scan_state;
            int prefix = 0;
            if (b == 0) {
                __threadfence();
                st[0] = ((long long)2 << 32) | (unsigned)block_total;
            } else {
                __threadfence();
                st[b] = ((long long)1 << 32) | (unsigned)block_total;
                int j = b - 1;
                while (j >= 0) {
                    long long s = st[j];
                    int flag = (int)(s >> 32);
                    if (flag == 2) { prefix += (int)(unsigned)s; break; }
                    if (flag == 1) { prefix += (int)(unsigned)s; j--; }
                }
                __threadfence();
                st[b] = ((long long)2 << 32) | (unsigned)(prefix + block_total);
            }
            s_prefix = prefix;
        }
        __syncthreads();

        int off = s_prefix + block_incl - v;
        if (i < N) {
            g_offset[i] = off;
            g_cursor[i] = off;
            if (i == N - 1) g_offset[N] = E;
        }
        __syncthreads();
        if (tid == 0) {
            __threadfence();
            int done = atomicAdd(&g_scan_count, 1);
            if (done == nscan - 1) atomicExch(&g_scan_done, 1);
        }
    }

    if (tid == 0) {
        while (atomicAdd(&g_scan_done, 0) == 0) { __nanosleep(64); }
        s_is64 = sniff_is64(ei);
    }
    __syncthreads();

    int t = b * SCAN_BLK + tid;
    if (t < E) {
        int s, d;
        if (s_is64) {
            s = (int)((const long long*)ei)[t];
            d = (int)((const long long*)ei)[(size_t)E + t];
        } else {
            s = ((const int*)ei)[t];
            d = ((const int*)ei)[(size_t)E + t];
        }
        int idx = atomicAdd(&g_cursor[d], 1);
        float4 ps = __ldg(&g_pos4[s]);
        float4 pd = __ldg(&g_pos4[d]);
        float4 er;
        er.x = __int_as_float(s);
        er.y = ps.x - pd.x;
        er.z = ps.y - pd.y;
        er.w = ps.z - pd.z;
        g_edge[idx] = er;
    }
}

// ---------------- per-destination-node attention: warp per node ----------------
__global__ __launch_bounds__(256, 6) void node_kernel(
    const float* __restrict__ W_pos,
    const float* __restrict__ b_pos,
    int N)
{
    const int warp = threadIdx.x >> 5;
    const int l = threadIdx.x & 31;
    const int n = blockIdx.x * 8 + warp;
    if (n >= N) return;

    const int c0 = 2 * l;
    const int h  = c0 >> 4;
    const int k0 = c0 & 15;
    const int k1 = k0 + 1;

    const float w00 = __ldg(&W_pos[h * 48 + 0  + k0]);
    const float w10 = __ldg(&W_pos[h * 48 + 16 + k0]);
    const float w20 = __ldg(&W_pos[h * 48 + 32 + k0]);
    const float b0  = __ldg(&b_pos[h * 16 + k0]);
    const float w01 = __ldg(&W_pos[h * 48 + 0  + k1]);
    const float w11 = __ldg(&W_pos[h * 48 + 16 + k1]);
    const float w21 = __ldg(&W_pos[h * 48 + 32 + k1]);
    const float b1  = __ldg(&b_pos[h * 16 + k1]);

    const int off = g_offset[n];
    const int end = g_offset[n + 1];

    float den0 = 0.f, den1 = 0.f, ac0 = 0.f, ac1 = 0.f;

    const float4* prow = (const float4*)g_projf;

#pragma unroll 4
    for (int e = off; e < end; e++) {
        float4 er = __ldg(&g_edge[e]);                       // broadcast
        int s = __float_as_int(er.x);
        float4 v = __ldg(&prow[(size_t)s * 32 + l]);         // {lin0, lin1, vaS0, vaS1}

        float d0 = fmaf(er.y, w00, fmaf(er.z, w10, fmaf(er.w, w20, b0)));
        float d1 = fmaf(er.y, w01, fmaf(er.z, w11, fmaf(er.w, w21, b1)));

        float e0 = ex2(fmaf(d0, LOG2E, v.z));
        float e1 = ex2(fmaf(d1, LOG2E, v.w));

        den0 += e0;
        den1 += e1;
        ac0 = fmaf(e0, v.x + d0, ac0);
        ac1 = fmaf(e1, v.y + d1, ac1);
    }

    float2 r;
    r.x = ac0 / (den0 + 1e-16f);
    r.y = ac1 / (den1 + 1e-16f);
    ((float2*)g_y)[(size_t)n * 32 + l] = r;
}

// ---------------- register-tiled MLP ----------------
__global__ __launch_bounds__(256) void mlp_kernel(
    const float* __restrict__ W1, const float* __restrict__ b1,
    const float* __restrict__ W2, const float* __restrict__ b2,
    float* __restrict__ out, int N)
{
    __shared__ float sy[64 * 64];
    __shared__ float sh_[64 * 64];
    __shared__ float sW[64 * 64];

    const int tid = threadIdx.x;
    const int og = tid >> 5;
    const int ng = tid & 31;
    const int base = blockIdx.x * 64;

    for (int f = tid; f < 64 * 16; f += 256) {
        int node = f >> 4;
        int j4 = f & 15;
        int gn = base + node;
        float4 v = (gn < N) ? ((const float4*)g_y)[(size_t)gn * 16 + j4]
                            : make_float4(0.f, 0.f, 0.f, 0.f);
        int cch = j4 * 4;
        sy[(cch + 0) * 64 + node] = v.x;
        sy[(cch + 1) * 64 + node] = v.y;
        sy[(cch + 2) * 64 + node] = v.z;
        sy[(cch + 3) * 64 + node] = v.w;
    }
    for (int f = tid; f < 1024; f += 256)
        ((float4*)sW)[f] = ((const float4*)W1)[f];
    __syncthreads();

    float acc[16];
    {
        float4 ba = *(const float4*)(b1 + og * 8);
        float4 bb = *(const float4*)(b1 + og * 8 + 4);
        acc[0]=ba.x; acc[1]=ba.y; acc[2]=ba.z; acc[3]=ba.w;
        acc[4]=bb.x; acc[5]=bb.y; acc[6]=bb.z; acc[7]=bb.w;
#pragma unroll
        for (int r = 0; r < 8; r++) acc[8 + r] = acc[r];
    }
#pragma unroll 8
    for (int k = 0; k < 64; k++) {
        float2 yv = *(const float2*)(sy + k * 64 + 2 * ng);
        float4 wa = *(const float4*)(sW + k * 64 + og * 8);
        float4 wb = *(const float4*)(sW + k * 64 + og * 8 + 4);
        acc[0]  = fmaf(yv.x, wa.x, acc[0]);
        acc[1]  = fmaf(yv.x, wa.y, acc[1]);
        acc[2]  = fmaf(yv.x, wa.z, acc[2]);
        acc[3]  = fmaf(yv.x, wa.w, acc[3]);
        acc[4]  = fmaf(yv.x, wb.x, acc[4]);
        acc[5]  = fmaf(yv.x, wb.y, acc[5]);
        acc[6]  = fmaf(yv.x, wb.z, acc[6]);
        acc[7]  = fmaf(yv.x, wb.w, acc[7]);
        acc[8]  = fmaf(yv.y, wa.x, acc[8]);
        acc[9]  = fmaf(yv.y, wa.y, acc[9]);
        acc[10] = fmaf(yv.y, wa.z, acc[10]);
        acc[11] = fmaf(yv.y, wa.w, acc[11]);
        acc[12] = fmaf(yv.y, wb.x, acc[12]);
        acc[13] = fmaf(yv.y, wb.y, acc[13]);
        acc[14] = fmaf(yv.y, wb.z, acc[14]);
        acc[15] = fmaf(yv.y, wb.w, acc[15]);
    }
#pragma unroll
    for (int oo = 0; oo < 8; oo++) {
        float2 hv;
        hv.x = fmaxf(acc[oo], 0.f);
        hv.y = fmaxf(acc[8 + oo], 0.f);
        *(float2*)(sh_ + (og * 8 + oo) * 64 + 2 * ng) = hv;
    }
    __syncthreads();

    for (int f = tid; f < 1024; f += 256)
        ((float4*)sW)[f] = ((const float4*)W2)[f];
    __syncthreads();

    {
        float4 ba = *(const float4*)(b2 + og * 8);
        float4 bb = *(const float4*)(b2 + og * 8 + 4);
        acc[0]=ba.x; acc[1]=ba.y; acc[2]=ba.z; acc[3]=ba.w;
        acc[4]=bb.x; acc[5]=bb.y; acc[6]=bb.z; acc[7]=bb.w;
#pragma unroll
        for (int r = 0; r < 8; r++) acc[8 + r] = acc[r];
    }
#pragma unroll 8
    for (int k = 0; k < 64; k++) {
        float2 hv = *(const float2*)(sh_ + k * 64 + 2 * ng);
        float4 wa = *(const float4*)(sW + k * 64 + og * 8);
        float4 wb = *(const float4*)(sW + k * 64 + og * 8 + 4);
        acc[0]  = fmaf(hv.x, wa.x, acc[0]);
        acc[1]  = fmaf(hv.x, wa.y, acc[1]);
        acc[2]  = fmaf(hv.x, wa.z, acc[2]);
        acc[3]  = fmaf(hv.x, wa.w, acc[3]);
        acc[4]  = fmaf(hv.x, wb.x, acc[4]);
        acc[5]  = fmaf(hv.x, wb.y, acc[5]);
        acc[6]  = fmaf(hv.x, wb.z, acc[6]);
        acc[7]  = fmaf(hv.x, wb.w, acc[7]);
        acc[8]  = fmaf(hv.y, wa.x, acc[8]);
        acc[9]  = fmaf(hv.y, wa.y, acc[9]);
        acc[10] = fmaf(hv.y, wa.z, acc[10]);
        acc[11] = fmaf(hv.y, wa.w, acc[11]);
        acc[12] = fmaf(hv.y, wb.x, acc[12]);
        acc[13] = fmaf(hv.y, wb.y, acc[13]);
        acc[14] = fmaf(hv.y, wb.z, acc[14]);
        acc[15] = fmaf(hv.y, wb.w, acc[15]);
    }

#pragma unroll
    for (int nn = 0; nn < 2; nn++) {
        int gn = base + 2 * ng + nn;
        if (gn < N) {
            float4 oa, ob;
            oa.x = acc[8 * nn + 0]; oa.y = acc[8 * nn + 1];
            oa.z = acc[8 * nn + 2]; oa.w = acc[8 * nn + 3];
            ob.x = acc[8 * nn + 4]; ob.y = acc[8 * nn + 5];
            ob.z = acc[8 * nn + 6]; ob.w = acc[8 * nn + 7];
            *(float4*)(out + (size_t)gn * 64 + og * 8)     = oa;
            *(float4*)(out + (size_t)gn * 64 + og * 8 + 4) = ob;
        }
    }
}

// ---------------- host ----------------
extern "C" void kernel_launch(void* const* d_in, const int* in_sizes, int n_in,
                              void* d_out, int out_size) {
    const float* x     = (const float*)d_in[0];
    const float* pos   = (const float*)d_in[1];
    const void*  ei    = d_in[2];
    const float* W_lin = (const float*)d_in[3];
    const float* W_src = (const float*)d_in[4];
    // d_in[5] = W_dst (cancels in the per-dst softmax)
    const float* W_pos = (const float*)d_in[6];
    const float* b_pos = (const float*)d_in[7];
    const float* W1    = (const float*)d_in[8];
    const float* b1    = (const float*)d_in[9];
    const float* W2    = (const float*)d_in[10];
    const float* b2    = (const float*)d_in[11];
    float* out = (float*)d_out;

    const int N = in_sizes[0] / 64;
    const int E = in_sizes[2] / 2;
    const int nscan = (N + SCAN_BLK - 1) / SCAN_BLK;
    int nss = (E + SCAN_BLK - 1) / SCAN_BLK;
    if (nss < nscan) nss = nscan;

    const int PB = (N + 63) / 64;                  // proj blocks
    const int HB = (E + 2047) / 2048;              // hist blocks

    zero_kernel<<<(N + 1023) / 1024, 1024>>>(N);
    projhist_kernel<<<PB + HB, 128>>>(x, pos, W_lin, W_src, ei, N, E, PB);
    scan_scatter_kernel<<<nss, SCAN_BLK>>>(ei, N, E, nscan);
    node_kernel<<<(N + 7) / 8, 256>>>(W_pos, b_pos, N);
    mlp_kernel<<<(N + 63) / 64, 256>>>(W1, b1, W2, b2, out, N);
}

// round 15
// speedup vs baseline: 1.0481x; 1.0101x over previous
#include <cuda_runtime.h>
#include <cstdint>

#define NMAX 100000
#define EMAX 3200000
#define SCAN_BLK 1024
#define LOG2E 1.4426950408889634f

// ---------------- device scratch ----------------
// per node: 128 floats; lane l owns float4 at [n*128+4l] = {lin[2l], lin[2l+1], asrc*log2e[2l], [2l+1]}
__device__ __align__(16) float  g_projf[(size_t)NMAX * 128];
__device__ __align__(16) float  g_y[(size_t)NMAX * 64];
__device__ __align__(16) float4 g_pos4[NMAX];
__device__ __align__(16) float4 g_edge[EMAX];   // {src_as_float, rx, ry, rz}
__device__ int g_count[NMAX];
__device__ int g_offset[NMAX + 1];
__device__ int g_cursor[NMAX];
__device__ long long g_scan_state[128];
__device__ int g_scan_count;
__device__ int g_scan_done;

__device__ __forceinline__ float ex2(float x) {
    float y;
    asm("ex2.approx.ftz.f32 %0, %1;" : "=f"(y) : "f"(x));
    return y;
}

__device__ __forceinline__ int sniff_is64(const void* ei) {
    const int* p = (const int*)ei;
    int is64 = 1;
#pragma unroll
    for (int i = 1; i < 16; i += 2)
        if (__ldg(&p[i]) != 0) is64 = 0;
    return is64;
}

// ---------------- zero: counters + scan state ----------------
__global__ void zero_kernel(int N) {
    int i = blockIdx.x * blockDim.x + threadIdx.x;
    if (i < N) g_count[i] = 0;
    if (i < 128) g_scan_state[i] = 0;
    if (i == 0) { g_scan_count = 0; g_scan_done = 0; }
}

// ---------------- fused proj (blocks < PB) + hist (blocks >= PB) ----------------
#define SX_STRIDE 68
__global__ __launch_bounds__(128) void projhist_kernel(
    const float* __restrict__ x,
    const float* __restrict__ pos,
    const float* __restrict__ W_lin,
    const float* __restrict__ W_src,
    const void* __restrict__ ei,
    int N, int E, int PB)
{
    if (blockIdx.x >= PB) {
        // ---- histogram role: 2048 edges per block ----
        __shared__ int s_is64;
        if (threadIdx.x == 0) s_is64 = sniff_is64(ei);
        __syncthreads();
        int base = (blockIdx.x - PB) * 2048;
        if (s_is64) {
            const long long* p = (const long long*)ei + E;
#pragma unroll 4
            for (int i = 0; i < 16; i++) {
                int t = base + i * 128 + threadIdx.x;
                if (t < E) atomicAdd(&g_count[(int)p[t]], 1);
            }
        } else {
            const int* p = (const int*)ei + E;
#pragma unroll 4
            for (int i = 0; i < 16; i++) {
                int t = base + i * 128 + threadIdx.x;
                if (t < E) atomicAdd(&g_count[p[t]], 1);
            }
        }
        return;
    }

    // ---- proj role: 64 nodes per block ----
    const int base = blockIdx.x * 64;

    if (threadIdx.x < 64) {
        int n = base + threadIdx.x;
        if (n < N)
            g_pos4[n] = make_float4(pos[3 * n + 0], pos[3 * n + 1], pos[3 * n + 2], 0.f);
    }

    const int c  = threadIdx.x;
    const int m  = c >> 6;            // 0 = lin, 1 = a_src (pre-scaled by log2e)
    const int cc = c & 63;
    const int h  = cc >> 4;
    const int k  = cc & 15;
    const int fidx = 4 * (cc >> 1) + (cc & 1) + 2 * m;
    const float scale = m ? LOG2E : 1.f;
    const float* W = m ? W_src : W_lin;

    float w[64];
#pragma unroll
    for (int j = 0; j < 64; j++) w[j] = __ldg(&W[h * 1024 + j * 16 + k]) * scale;

    __shared__ float sx[64 * SX_STRIDE];

    for (int f = threadIdx.x; f < 64 * 16; f += 128) {
        int node = f >> 4;
        int j4 = f & 15;
        int gn = base + node;
        if (gn >= N) gn = N - 1;
        float4 v = ((const float4*)x)[(size_t)gn * 16 + j4];
        int j = j4 * 4;
        sx[(j + 0) * SX_STRIDE + node] = v.x;
        sx[(j + 1) * SX_STRIDE + node] = v.y;
        sx[(j + 2) * SX_STRIDE + node] = v.z;
        sx[(j + 3) * SX_STRIDE + node] = v.w;
    }
    __syncthreads();

#pragma unroll
    for (int p = 0; p < 2; p++) {
        float acc[32];
#pragma unroll
        for (int r = 0; r < 32; r++) acc[r] = 0.f;
        for (int j = 0; j < 64; j++) {
            const float4* row = (const float4*)(sx + j * SX_STRIDE + p * 32);
            float wj = w[j];
#pragma unroll
            for (int q = 0; q < 8; q++) {
                float4 v = row[q];
                acc[q * 4 + 0] = fmaf(v.x, wj, acc[q * 4 + 0]);
                acc[q * 4 + 1] = fmaf(v.y, wj, acc[q * 4 + 1]);
                acc[q * 4 + 2] = fmaf(v.z, wj, acc[q * 4 + 2]);
                acc[q * 4 + 3] = fmaf(v.w, wj, acc[q * 4 + 3]);
            }
        }
#pragma unroll
        for (int r = 0; r < 32; r++) {
            int gn = base + p * 32 + r;
            if (gn < N) g_projf[(size_t)gn * 128 + fidx] = acc[r];
        }
    }
}

// ---------------- fused scan (decoupled lookback) + scatter edge records ----------------
__global__ __launch_bounds__(SCAN_BLK) void scan_scatter_kernel(
    const void* __restrict__ ei, int N, int E, int nscan)
{
    __shared__ int s_warp[32];
    __shared__ int s_prefix;
    __shared__ int s_is64;

    const int tid = threadIdx.x;
    const int b = blockIdx.x;
    const int lane = tid & 31;
    const int wid = tid >> 5;

    if (b < nscan) {
        const int i = b * SCAN_BLK + tid;
        int v = (i < N) ? g_count[i] : 0;

        int incl = v;
#pragma unroll
        for (int ofs = 1; ofs < 32; ofs <<= 1) {
            int t = __shfl_up_sync(0xffffffffu, incl, ofs);
            if (lane >= ofs) incl += t;
        }
        if (lane == 31) s_warp[wid] = incl;
        __syncthreads();

        if (wid == 0) {
            int wv = s_warp[lane];
#pragma unroll
            for (int ofs = 1; ofs < 32; ofs <<= 1) {
                int t = __shfl_up_sync(0xffffffffu, wv, ofs);
                if (lane >= ofs) wv += t;
            }
            s_warp[lane] = wv;
        }
        __syncthreads();

        int warp_excl = (wid == 0) ? 0 : s_warp[wid - 1];
        int block_incl = incl + warp_excl;
        int block_total = s_warp[31];

        if (tid == 0) {
            volatile long long* st = (volatile long long*)g_scan_state;
            int prefix = 0;
            if (b == 0) {
                __threadfence();
                st[0] = ((long long)2 << 32) | (unsigned)block_total;
            } else {
                __threadfence();
                st[b] = ((long long)1 << 32) | (unsigned)block_total;
                int j = b - 1;
                while (j >= 0) {
                    long long s = st[j];
                    int flag = (int)(s >> 32);
                    if (flag == 2) { prefix += (int)(unsigned)s; break; }
                    if (flag == 1) { prefix += (int)(unsigned)s; j--; }
                }
                __threadfence();
                st[b] = ((long long)2 << 32) | (unsigned)(prefix + block_total);
            }
            s_prefix = prefix;
        }
        __syncthreads();

        int off = s_prefix + block_incl - v;
        if (i < N) {
            g_offset[i] = off;
            g_cursor[i] = off;
            if (i == N - 1) g_offset[N] = E;
        }
        __syncthreads();
        if (tid == 0) {
            __threadfence();
            int done = atomicAdd(&g_scan_count, 1);
            if (done == nscan - 1) atomicExch(&g_scan_done, 1);
        }
    }

    if (tid == 0) {
        while (atomicAdd(&g_scan_done, 0) == 0) { __nanosleep(64); }
        s_is64 = sniff_is64(ei);
    }
    __syncthreads();

    int t = b * SCAN_BLK + tid;
    if (t < E) {
        int s, d;
        if (s_is64) {
            s = (int)((const long long*)ei)[t];
            d = (int)((const long long*)ei)[(size_t)E + t];
        } else {
            s = ((const int*)ei)[t];
            d = ((const int*)ei)[(size_t)E + t];
        }
        int idx = atomicAdd(&g_cursor[d], 1);
        float4 ps = __ldg(&g_pos4[s]);
        float4 pd = __ldg(&g_pos4[d]);
        float4 er;
        er.x = __int_as_float(s);
        er.y = ps.x - pd.x;
        er.z = ps.y - pd.y;
        er.w = ps.z - pd.z;
        g_edge[idx] = er;
    }
}

// ---------------- per-destination-node attention: warp per node ----------------
__global__ __launch_bounds__(256, 6) void node_kernel(
    const float* __restrict__ W_pos,
    const float* __restrict__ b_pos,
    int N)
{
    const int warp = threadIdx.x >> 5;
    const int l = threadIdx.x & 31;
    const int n = blockIdx.x * 8 + warp;
    if (n >= N) return;

    const int c0 = 2 * l;
    const int h  = c0 >> 4;
    const int k0 = c0 & 15;
    const int k1 = k0 + 1;

    const float w00 = __ldg(&W_pos[h * 48 + 0  + k0]);
    const float w10 = __ldg(&W_pos[h * 48 + 16 + k0]);
    const float w20 = __ldg(&W_pos[h * 48 + 32 + k0]);
    const float b0  = __ldg(&b_pos[h * 16 + k0]);
    const float w01 = __ldg(&W_pos[h * 48 + 0  + k1]);
    const float w11 = __ldg(&W_pos[h * 48 + 16 + k1]);
    const float w21 = __ldg(&W_pos[h * 48 + 32 + k1]);
    const float b1  = __ldg(&b_pos[h * 16 + k1]);

    const int off = g_offset[n];
    const int end = g_offset[n + 1];

    float den0 = 0.f, den1 = 0.f, ac0 = 0.f, ac1 = 0.f;

    const float4* prow = (const float4*)g_projf;

#pragma unroll 4
    for (int e = off; e < end; e++) {
        float4 er = __ldg(&g_edge[e]);                       // broadcast
        int s = __float_as_int(er.x);
        float4 v = __ldg(&prow[(size_t)s * 32 + l]);         // {lin0, lin1, vaS0, vaS1}

        float d0 = fmaf(er.y, w00, fmaf(er.z, w10, fmaf(er.w, w20, b0)));
        float d1 = fmaf(er.y, w01, fmaf(er.z, w11, fmaf(er.w, w21, b1)));

        float e0 = ex2(fmaf(d0, LOG2E, v.z));
        float e1 = ex2(fmaf(d1, LOG2E, v.w));

        den0 += e0;
        den1 += e1;
        ac0 = fmaf(e0, v.x + d0, ac0);
        ac1 = fmaf(e1, v.y + d1, ac1);
    }

    float2 r;
    r.x = ac0 / (den0 + 1e-16f);
    r.y = ac1 / (den1 + 1e-16f);
    ((float2*)g_y)[(size_t)n * 32 + l] = r;
}

// ---------------- register-tiled MLP ----------------
__global__ __launch_bounds__(256) void mlp_kernel(
    const float* __restrict__ W1, const float* __restrict__ b1,
    const float* __restrict__ W2, const float* __restrict__ b2,
    float* __restrict__ out, int N)
{
    __shared__ float sy[64 * 64];
    __shared__ float sh_[64 * 64];
    __shared__ float sW[64 * 64];

    const int tid = threadIdx.x;
    const int og = tid >> 5;
    const int ng = tid & 31;
    const int base = blockIdx.x * 64;

    for (int f = tid; f < 64 * 16; f += 256) {
        int node = f >> 4;
        int j4 = f & 15;
        int gn = base + node;
        float4 v = (gn < N) ? ((const float4*)g_y)[(size_t)gn * 16 + j4]
                            : make_float4(0.f, 0.f, 0.f, 0.f);
        int cch = j4 * 4;
        sy[(cch + 0) * 64 + node] = v.x;
        sy[(cch + 1) * 64 + node] = v.y;
        sy[(cch + 2) * 64 + node] = v.z;
        sy[(cch + 3) * 64 + node] = v.w;
    }
    for (int f = tid; f < 1024; f += 256)
        ((float4*)sW)[f] = ((const float4*)W1)[f];
    __syncthreads();

    float acc[16];
    {
        float4 ba = *(const float4*)(b1 + og * 8);
        float4 bb = *(const float4*)(b1 + og * 8 + 4);
        acc[0]=ba.x; acc[1]=ba.y; acc[2]=ba.z; acc[3]=ba.w;
        acc[4]=bb.x; acc[5]=bb.y; acc[6]=bb.z; acc[7]=bb.w;
#pragma unroll
        for (int r = 0; r < 8; r++) acc[8 + r] = acc[r];
    }
#pragma unroll 8
    for (int k = 0; k < 64; k++) {
        float2 yv = *(const float2*)(sy + k * 64 + 2 * ng);
        float4 wa = *(const float4*)(sW + k * 64 + og * 8);
        float4 wb = *(const float4*)(sW + k * 64 + og * 8 + 4);
        acc[0]  = fmaf(yv.x, wa.x, acc[0]);
        acc[1]  = fmaf(yv.x, wa.y, acc[1]);
        acc[2]  = fmaf(yv.x, wa.z, acc[2]);
        acc[3]  = fmaf(yv.x, wa.w, acc[3]);
        acc[4]  = fmaf(yv.x, wb.x, acc[4]);
        acc[5]  = fmaf(yv.x, wb.y, acc[5]);
        acc[6]  = fmaf(yv.x, wb.z, acc[6]);
        acc[7]  = fmaf(yv.x, wb.w, acc[7]);
        acc[8]  = fmaf(yv.y, wa.x, acc[8]);
        acc[9]  = fmaf(yv.y, wa.y, acc[9]);
        acc[10] = fmaf(yv.y, wa.z, acc[10]);
        acc[11] = fmaf(yv.y, wa.w, acc[11]);
        acc[12] = fmaf(yv.y, wb.x, acc[12]);
        acc[13] = fmaf(yv.y, wb.y, acc[13]);
        acc[14] = fmaf(yv.y, wb.z, acc[14]);
        acc[15] = fmaf(yv.y, wb.w, acc[15]);
    }
#pragma unroll
    for (int oo = 0; oo < 8; oo++) {
        float2 hv;
        hv.x = fmaxf(acc[oo], 0.f);
        hv.y = fmaxf(acc[8 + oo], 0.f);
        *(float2*)(sh_ + (og * 8 + oo) * 64 + 2 * ng) = hv;
    }
    __syncthreads();

    for (int f = tid; f < 1024; f += 256)
        ((float4*)sW)[f] = ((const float4*)W2)[f];
    __syncthreads();

    {
        float4 ba = *(const float4*)(b2 + og * 8);
        float4 bb = *(const float4*)(b2 + og * 8 + 4);
        acc[0]=ba.x; acc[1]=ba.y; acc[2]=ba.z; acc[3]=ba.w;
        acc[4]=bb.x; acc[5]=bb.y; acc[6]=bb.z; acc[7]=bb.w;
#pragma unroll
        for (int r = 0; r < 8; r++) acc[8 + r] = acc[r];
    }
#pragma unroll 8
    for (int k = 0; k < 64; k++) {
        float2 hv = *(const float2*)(sh_ + k * 64 + 2 * ng);
        float4 wa = *(const float4*)(sW + k * 64 + og * 8);
        float4 wb = *(const float4*)(sW + k * 64 + og * 8 + 4);
        acc[0]  = fmaf(hv.x, wa.x, acc[0]);
        acc[1]  = fmaf(hv.x, wa.y, acc[1]);
        acc[2]  = fmaf(hv.x, wa.z, acc[2]);
        acc[3]  = fmaf(hv.x, wa.w, acc[3]);
        acc[4]  = fmaf(hv.x, wb.x, acc[4]);
        acc[5]  = fmaf(hv.x, wb.y, acc[5]);
        acc[6]  = fmaf(hv.x, wb.z, acc[6]);
        acc[7]  = fmaf(hv.x, wb.w, acc[7]);
        acc[8]  = fmaf(hv.y, wa.x, acc[8]);
        acc[9]  = fmaf(hv.y, wa.y, acc[9]);
        acc[10] = fmaf(hv.y, wa.z, acc[10]);
        acc[11] = fmaf(hv.y, wa.w, acc[11]);
        acc[12] = fmaf(hv.y, wb.x, acc[12]);
        acc[13] = fmaf(hv.y, wb.y, acc[13]);
        acc[14] = fmaf(hv.y, wb.z, acc[14]);
        acc[15] = fmaf(hv.y, wb.w, acc[15]);
    }

#pragma unroll
    for (int nn = 0; nn < 2; nn++) {
        int gn = base + 2 * ng + nn;
        if (gn < N) {
            float4 oa, ob;
            oa.x = acc[8 * nn + 0]; oa.y = acc[8 * nn + 1];
            oa.z = acc[8 * nn + 2]; oa.w = acc[8 * nn + 3];
            ob.x = acc[8 * nn + 4]; ob.y = acc[8 * nn + 5];
            ob.z = acc[8 * nn + 6]; ob.w = acc[8 * nn + 7];
            *(float4*)(out + (size_t)gn * 64 + og * 8)     = oa;
            *(float4*)(out + (size_t)gn * 64 + og * 8 + 4) = ob;
        }
    }
}

// ---------------- host ----------------
extern "C" void kernel_launch(void* const* d_in, const int* in_sizes, int n_in,
                              void* d_out, int out_size) {
    const float* x     = (const float*)d_in[0];
    const float* pos   = (const float*)d_in[1];
    const void*  ei    = d_in[2];
    const float* W_lin = (const float*)d_in[3];
    const float* W_src = (const float*)d_in[4];
    // d_in[5] = W_dst (cancels in the per-dst softmax)
    const float* W_pos = (const float*)d_in[6];
    const float* b_pos = (const float*)d_in[7];
    const float* W1    = (const float*)d_in[8];
    const float* b1    = (const float*)d_in[9];
    const float* W2    = (const float*)d_in[10];
    const float* b2    = (const float*)d_in[11];
    float* out = (float*)d_out;

    const int N = in_sizes[0] / 64;
    const int E = in_sizes[2] / 2;
    const int nscan = (N + SCAN_BLK - 1) / SCAN_BLK;
    int nss = (E + SCAN_BLK - 1) / SCAN_BLK;
    if (nss < nscan) nss = nscan;

    const int PB = (N + 63) / 64;                  // proj blocks
    const int HB = (E + 2047) / 2048;              // hist blocks

    zero_kernel<<<(N + 1023) / 1024, 1024>>>(N);
    projhist_kernel<<<PB + HB, 128>>>(x, pos, W_lin, W_src, ei, N, E, PB);
    scan_scatter_kernel<<<nss, SCAN_BLK>>>(ei, N, E, nscan);
    node_kernel<<<(N + 7) / 8, 256>>>(W_pos, b_pos, N);
    mlp_kernel<<<(N + 63) / 64, 256>>>(W1, b1, W2, b2, out, N);
}